// round 5
// baseline (speedup 1.0000x reference)
#include <cuda_runtime.h>
#include <math.h>

#define BB 2
#define LL 2048
#define DM 256
#define HH 8
#define DHD 32

// Scratch (allocation-free rule: device globals)
__device__ float g_Q[BB*LL*DM];
__device__ float g_K[BB*LL*DM];
__device__ float g_V[BB*LL*DM];
__device__ float g_O[BB*LL*DM];

// P[M x 256] = X[M x 256] @ W^T, W is [256 x 256] row-major.
// Block computes 64x64 tile, 256 threads, 4x4 microtile each, BK=16.
__global__ __launch_bounds__(256) void gemm_nt(const float* __restrict__ X,
                                               const float* __restrict__ W,
                                               float* __restrict__ P) {
    __shared__ float Xs[16][64];
    __shared__ float Ws[16][64];
    const int tid = threadIdx.x;
    const int tx = tid & 15, ty = tid >> 4;
    const int rowBase = blockIdx.y * 64;
    const int colBase = blockIdx.x * 64;
    const int lr = tid >> 2;          // 0..63
    const int lc = (tid & 3) * 4;     // 0,4,8,12
    float acc[4][4] = {};
    for (int k0 = 0; k0 < 256; k0 += 16) {
        float4 xv = *(const float4*)&X[(rowBase + lr) * DM + k0 + lc];
        float4 wv = *(const float4*)&W[(colBase + lr) * DM + k0 + lc];
        __syncthreads();
        Xs[lc+0][lr] = xv.x; Xs[lc+1][lr] = xv.y; Xs[lc+2][lr] = xv.z; Xs[lc+3][lr] = xv.w;
        Ws[lc+0][lr] = wv.x; Ws[lc+1][lr] = wv.y; Ws[lc+2][lr] = wv.z; Ws[lc+3][lr] = wv.w;
        __syncthreads();
        #pragma unroll
        for (int k = 0; k < 16; k++) {
            float4 av = *(const float4*)&Xs[k][ty*4];
            float4 bv = *(const float4*)&Ws[k][tx*4];
            float a[4] = {av.x, av.y, av.z, av.w};
            float b[4] = {bv.x, bv.y, bv.z, bv.w};
            #pragma unroll
            for (int i = 0; i < 4; i++)
                #pragma unroll
                for (int j = 0; j < 4; j++)
                    acc[i][j] += a[i] * b[j];
        }
    }
    #pragma unroll
    for (int i = 0; i < 4; i++)
        #pragma unroll
        for (int j = 0; j < 4; j++)
            P[(rowBase + ty*4 + i) * DM + colBase + tx*4 + j] = acc[i][j];
}

// One warp per query row. blockIdx.x = b*H+h (16), blockIdx.y = q-chunk (256), 8 warps.
__global__ __launch_bounds__(256) void attn_kernel(const int*   __restrict__ mask,
                                                   const float* __restrict__ Amat,
                                                   const float* __restrict__ Dmat,
                                                   const float* __restrict__ wA,
                                                   const float* __restrict__ wD,
                                                   float* __restrict__ attn_out) {
    __shared__ float Ks[128][36];   // padded: (row*36 + 4i)/4 = 9*row + i -> conflict-free float4
    __shared__ float sQ[8][32];
    const int bh = blockIdx.x;
    const int b = bh >> 3, h = bh & 7;
    const int warp = threadIdx.x >> 5, lane = threadIdx.x & 31;
    const int q = blockIdx.y * 8 + warp;

    sQ[warp][lane] = g_Q[((size_t)b*LL + q) * DM + h*DHD + lane];
    __syncwarp();
    float qv[32];
    #pragma unroll
    for (int i = 0; i < 32; i++) qv[i] = sQ[warp][i];

    const float* Khead = g_K + (size_t)b*LL*DM + h*DHD;
    const float* Vhead = g_V + (size_t)b*LL*DM + h*DHD;

    float sc[64];
    // -------- Phase A: scores = Q . K --------
    #pragma unroll
    for (int kt = 0; kt < 16; kt++) {
        __syncthreads();
        #pragma unroll
        for (int idx = 0; idx < 16; idx++) {
            int t = idx * 256 + threadIdx.x;
            int r = t >> 5, d = t & 31;
            Ks[r][d] = Khead[(size_t)(kt*128 + r) * DM + d];
        }
        __syncthreads();
        #pragma unroll
        for (int kk = 0; kk < 4; kk++) {
            const float4* Kr = (const float4*)&Ks[kk*32 + lane][0];
            float s = 0.f;
            #pragma unroll
            for (int i = 0; i < 8; i++) {
                float4 kv = Kr[i];
                s += qv[4*i]*kv.x + qv[4*i+1]*kv.y + qv[4*i+2]*kv.z + qv[4*i+3]*kv.w;
            }
            sc[kt*4 + kk] = s;
        }
    }

    // -------- Phase A2: mask/adjacency/distance modulation + softmax --------
    const float wAh = wA[h], wDh = wD[h];
    const float invscale = 0.17677669529663687f;  // 1/sqrt(32)
    const size_t rowbase = ((size_t)b*LL + q) * LL;
    float mx = -1e30f;
    #pragma unroll
    for (int r = 0; r < 64; r++) {
        int k = (r >> 2)*128 + (r & 3)*32 + lane;
        float s = (mask[rowbase + k] == 1) ? sc[r] : 0.f;
        float f = 1.f + Amat[rowbase + k]*wAh + Dmat[rowbase + k]*wDh;
        float lg = s * f * invscale;
        sc[r] = lg;
        mx = fmaxf(mx, lg);
    }
    #pragma unroll
    for (int off = 16; off; off >>= 1)
        mx = fmaxf(mx, __shfl_xor_sync(0xffffffffu, mx, off));
    float sum = 0.f;
    #pragma unroll
    for (int r = 0; r < 64; r++) { float p = __expf(sc[r] - mx); sc[r] = p; sum += p; }
    #pragma unroll
    for (int off = 16; off; off >>= 1)
        sum += __shfl_xor_sync(0xffffffffu, sum, off);
    const float inv = 1.f / sum;
    const size_t arow = ((size_t)bh*LL + q) * LL;
    #pragma unroll
    for (int r = 0; r < 64; r++) {
        sc[r] *= inv;
        int k = (r >> 2)*128 + (r & 3)*32 + lane;
        attn_out[arow + k] = sc[r];
    }

    // -------- Phase B: out = attn @ V --------
    float acc[32];
    #pragma unroll
    for (int d = 0; d < 32; d++) acc[d] = 0.f;
    #pragma unroll
    for (int kt = 0; kt < 16; kt++) {
        __syncthreads();
        #pragma unroll
        for (int idx = 0; idx < 16; idx++) {
            int t = idx * 256 + threadIdx.x;
            int r = t >> 5, d = t & 31;
            Ks[r][d] = Vhead[(size_t)(kt*128 + r) * DM + d];
        }
        __syncthreads();
        #pragma unroll
        for (int kk = 0; kk < 4; kk++) {
            float a = sc[kt*4 + kk];
            const float4* Vr = (const float4*)&Ks[kk*32 + lane][0];
            #pragma unroll
            for (int i = 0; i < 8; i++) {
                float4 vv = Vr[i];
                acc[4*i]   += a * vv.x;
                acc[4*i+1] += a * vv.y;
                acc[4*i+2] += a * vv.z;
                acc[4*i+3] += a * vv.w;
            }
        }
    }
    // Rotating cross-lane reduction: lane d ends with out[d]
    float myout = 0.f;
    #pragma unroll
    for (int d = 0; d < 32; d++) {
        float v = acc[d];
        #pragma unroll
        for (int off = 16; off; off >>= 1)
            v += __shfl_xor_sync(0xffffffffu, v, off);
        if (lane == d) myout = v;
    }
    g_O[((size_t)b*LL + q) * DM + h*DHD + lane] = myout;
}

extern "C" void kernel_launch(void* const* d_in, const int* in_sizes, int n_in,
                              void* d_out, int out_size) {
    (void)in_sizes; (void)n_in; (void)out_size;
    const float* queries = (const float*)d_in[0];
    const float* keys    = (const float*)d_in[1];
    const float* values  = (const float*)d_in[2];
    const int*   amask   = (const int*)  d_in[3];
    const float* adj     = (const float*)d_in[4];
    const float* dist    = (const float*)d_in[5];
    const float* Wq      = (const float*)d_in[6];
    const float* Wk      = (const float*)d_in[7];
    const float* Wv      = (const float*)d_in[8];
    const float* Wo      = (const float*)d_in[9];
    const float* wA      = (const float*)d_in[10];
    const float* wD      = (const float*)d_in[11];

    float *dQ, *dK, *dV, *dO;
    cudaGetSymbolAddress((void**)&dQ, g_Q);
    cudaGetSymbolAddress((void**)&dK, g_K);
    cudaGetSymbolAddress((void**)&dV, g_V);
    cudaGetSymbolAddress((void**)&dO, g_O);

    float* out_proj = (float*)d_out;                       // (B, L, 256)
    float* out_attn = (float*)d_out + (size_t)BB*LL*DM;    // (B, H, L, L)

    dim3 gemmGrid(DM/64, (BB*LL)/64);   // (4, 64)
    gemm_nt<<<gemmGrid, 256>>>(queries, Wq, dQ);
    gemm_nt<<<gemmGrid, 256>>>(keys,    Wk, dK);
    gemm_nt<<<gemmGrid, 256>>>(values,  Wv, dV);

    attn_kernel<<<dim3(BB*HH, LL/8), 256>>>(amask, adj, dist, wA, wD, out_attn);

    gemm_nt<<<gemmGrid, 256>>>(dO, Wo, out_proj);
}

// round 6
// speedup vs baseline: 1.4037x; 1.4037x over previous
#include <cuda_runtime.h>
#include <math.h>

#define BB 2
#define LL 2048
#define DM 256
#define HH 8
#define DHD 32
#define INVSCALE 0.17677669529663687f   // 1/sqrt(32)

// Scratch (allocation-free rule: device globals)
__device__ float g_Q[BB*LL*DM];
__device__ float g_K[BB*LL*DM];
__device__ float g_V[BB*LL*DM];
__device__ float g_O[BB*LL*DM];

// P[M x 256] = X[M x 256] @ W^T, W is [256 x 256] row-major.
// Block computes 64x64 tile, 256 threads, 4x4 microtile each, BK=16.
__global__ __launch_bounds__(256) void gemm_nt(const float* __restrict__ X,
                                               const float* __restrict__ W,
                                               float* __restrict__ P) {
    __shared__ float Xs[16][64];
    __shared__ float Ws[16][64];
    const int tid = threadIdx.x;
    const int tx = tid & 15, ty = tid >> 4;
    const int rowBase = blockIdx.y * 64;
    const int colBase = blockIdx.x * 64;
    const int lr = tid >> 2;          // 0..63
    const int lc = (tid & 3) * 4;     // 0,4,8,12
    float acc[4][4] = {};
    for (int k0 = 0; k0 < 256; k0 += 16) {
        float4 xv = *(const float4*)&X[(rowBase + lr) * DM + k0 + lc];
        float4 wv = *(const float4*)&W[(colBase + lr) * DM + k0 + lc];
        __syncthreads();
        Xs[lc+0][lr] = xv.x; Xs[lc+1][lr] = xv.y; Xs[lc+2][lr] = xv.z; Xs[lc+3][lr] = xv.w;
        Ws[lc+0][lr] = wv.x; Ws[lc+1][lr] = wv.y; Ws[lc+2][lr] = wv.z; Ws[lc+3][lr] = wv.w;
        __syncthreads();
        #pragma unroll
        for (int k = 0; k < 16; k++) {
            float4 av = *(const float4*)&Xs[k][ty*4];
            float4 bv = *(const float4*)&Ws[k][tx*4];
            float a[4] = {av.x, av.y, av.z, av.w};
            float b[4] = {bv.x, bv.y, bv.z, bv.w};
            #pragma unroll
            for (int i = 0; i < 4; i++)
                #pragma unroll
                for (int j = 0; j < 4; j++)
                    acc[i][j] += a[i] * b[j];
        }
    }
    #pragma unroll
    for (int i = 0; i < 4; i++)
        #pragma unroll
        for (int j = 0; j < 4; j++)
            P[(rowBase + ty*4 + i) * DM + colBase + tx*4 + j] = acc[i][j];
}

// ---------------------------------------------------------------------------
// Pass 1: modulated logits = (mask ? Q.K : 0) * (1 + A*wA + D*wD) * invscale
// Written directly into the attn region of d_out.
// Block: 64 queries x 64 keys, 256 threads, 4x4 microtile, k=32 fully resident.
// Grid: x = h (8, innermost so heads share mask/A/D tiles in L2),
//       y = k-tile (32), z = b*32 + q-tile (64).
// ---------------------------------------------------------------------------
__global__ __launch_bounds__(256) void attn_scores_kernel(
    const int*   __restrict__ mask,
    const float* __restrict__ Amat,
    const float* __restrict__ Dmat,
    const float* __restrict__ wA,
    const float* __restrict__ wD,
    float*       __restrict__ attn_out)
{
    __shared__ float Qs[64*33];
    __shared__ float Ks[64*33];
    const int h  = blockIdx.x;
    const int kt = blockIdx.y;
    const int b  = blockIdx.z >> 5;
    const int qt = blockIdx.z & 31;
    const int t  = threadIdx.x;
    const int tx = t & 15, ty = t >> 4;

    // Load Q tile (64 x 32) and K tile (64 x 32), stride-33 smem (bank-clean)
    {
        const int r  = t >> 2;         // 0..63
        const int c0 = (t & 3) * 8;    // 0,8,16,24
        const float* Qg = g_Q + ((size_t)(b*LL + qt*64 + r))*DM + h*DHD + c0;
        const float* Kg = g_K + ((size_t)(b*LL + kt*64 + r))*DM + h*DHD + c0;
        float4 q0 = ((const float4*)Qg)[0], q1 = ((const float4*)Qg)[1];
        float4 k0 = ((const float4*)Kg)[0], k1 = ((const float4*)Kg)[1];
        float* qd = &Qs[r*33 + c0];
        qd[0]=q0.x; qd[1]=q0.y; qd[2]=q0.z; qd[3]=q0.w;
        qd[4]=q1.x; qd[5]=q1.y; qd[6]=q1.z; qd[7]=q1.w;
        float* kd = &Ks[r*33 + c0];
        kd[0]=k0.x; kd[1]=k0.y; kd[2]=k0.z; kd[3]=k0.w;
        kd[4]=k1.x; kd[5]=k1.y; kd[6]=k1.z; kd[7]=k1.w;
    }
    __syncthreads();

    float acc[4][4] = {};
    #pragma unroll
    for (int kk = 0; kk < 32; kk++) {
        float a0 = Qs[(ty*4+0)*33 + kk];
        float a1 = Qs[(ty*4+1)*33 + kk];
        float a2 = Qs[(ty*4+2)*33 + kk];
        float a3 = Qs[(ty*4+3)*33 + kk];
        float b0 = Ks[(tx*4+0)*33 + kk];
        float b1 = Ks[(tx*4+1)*33 + kk];
        float b2 = Ks[(tx*4+2)*33 + kk];
        float b3 = Ks[(tx*4+3)*33 + kk];
        acc[0][0] += a0*b0; acc[0][1] += a0*b1; acc[0][2] += a0*b2; acc[0][3] += a0*b3;
        acc[1][0] += a1*b0; acc[1][1] += a1*b1; acc[1][2] += a1*b2; acc[1][3] += a1*b3;
        acc[2][0] += a2*b0; acc[2][1] += a2*b1; acc[2][2] += a2*b2; acc[2][3] += a2*b3;
        acc[3][0] += a3*b0; acc[3][1] += a3*b1; acc[3][2] += a3*b2; acc[3][3] += a3*b3;
    }

    // Epilogue: mask + modulation + scale, write logits to attn region
    const float wAh = wA[h], wDh = wD[h];
    const int  kcol = kt*64 + tx*4;
    #pragma unroll
    for (int i = 0; i < 4; i++) {
        const int q = qt*64 + ty*4 + i;
        const size_t rowoff = ((size_t)b*LL + q)*LL + kcol;
        int4   m  = *(const int4*)  &mask[rowoff];
        float4 av = *(const float4*)&Amat[rowoff];
        float4 dv = *(const float4*)&Dmat[rowoff];
        float4 o;
        o.x = ((m.x==1) ? acc[i][0] : 0.f) * (1.f + av.x*wAh + dv.x*wDh) * INVSCALE;
        o.y = ((m.y==1) ? acc[i][1] : 0.f) * (1.f + av.y*wAh + dv.y*wDh) * INVSCALE;
        o.z = ((m.z==1) ? acc[i][2] : 0.f) * (1.f + av.z*wAh + dv.z*wDh) * INVSCALE;
        o.w = ((m.w==1) ? acc[i][3] : 0.f) * (1.f + av.w*wAh + dv.w*wDh) * INVSCALE;
        const size_t arow = ((size_t)(b*HH + h)*LL + q)*LL + kcol;
        *(float4*)&attn_out[arow] = o;
    }
}

// ---------------------------------------------------------------------------
// Pass 2: in-place row softmax over 2048 logits. One block per row.
// ---------------------------------------------------------------------------
__global__ __launch_bounds__(256) void softmax_kernel(float* __restrict__ attn)
{
    __shared__ float redm[8];
    __shared__ float reds[8];
    float4* p = (float4*)(attn + (size_t)blockIdx.x * LL);
    const int t = threadIdx.x;
    const int lane = t & 31, warp = t >> 5;

    float4 v0 = p[t];
    float4 v1 = p[t + 256];
    float mx = fmaxf(fmaxf(fmaxf(v0.x, v0.y), fmaxf(v0.z, v0.w)),
                     fmaxf(fmaxf(v1.x, v1.y), fmaxf(v1.z, v1.w)));
    #pragma unroll
    for (int off = 16; off; off >>= 1)
        mx = fmaxf(mx, __shfl_xor_sync(0xffffffffu, mx, off));
    if (lane == 0) redm[warp] = mx;
    __syncthreads();
    mx = redm[0];
    #pragma unroll
    for (int w = 1; w < 8; w++) mx = fmaxf(mx, redm[w]);

    v0.x = __expf(v0.x - mx); v0.y = __expf(v0.y - mx);
    v0.z = __expf(v0.z - mx); v0.w = __expf(v0.w - mx);
    v1.x = __expf(v1.x - mx); v1.y = __expf(v1.y - mx);
    v1.z = __expf(v1.z - mx); v1.w = __expf(v1.w - mx);
    float sum = v0.x + v0.y + v0.z + v0.w + v1.x + v1.y + v1.z + v1.w;
    #pragma unroll
    for (int off = 16; off; off >>= 1)
        sum += __shfl_xor_sync(0xffffffffu, sum, off);
    if (lane == 0) reds[warp] = sum;
    __syncthreads();
    sum = reds[0];
    #pragma unroll
    for (int w = 1; w < 8; w++) sum += reds[w];
    const float inv = 1.f / sum;

    v0.x *= inv; v0.y *= inv; v0.z *= inv; v0.w *= inv;
    v1.x *= inv; v1.y *= inv; v1.z *= inv; v1.w *= inv;
    p[t] = v0;
    p[t + 256] = v1;
}

// ---------------------------------------------------------------------------
// Pass 3: O = attn @ V. Block: 64 queries x 32 dims, 128 threads, 4x4 microtile.
// k-loop over 2048 in chunks of 32. V tile reused across 64 queries, L2-hot.
// Grid: x = q-tile (32), y = bh (16).
// ---------------------------------------------------------------------------
__global__ __launch_bounds__(128) void pv_kernel(const float* __restrict__ attn)
{
    __shared__ float As[64*33];
    __shared__ float Vs[32*33];
    const int qt = blockIdx.x;
    const int bh = blockIdx.y;
    const int b = bh >> 3, h = bh & 7;
    const int t = threadIdx.x;
    const int tx = t & 7;    // d group (x4)
    const int ty = t >> 3;   // 0..15, q group (x4)

    const float* arow  = attn + ((size_t)bh*LL + qt*64)*LL;
    const float* Vhead = g_V + (size_t)b*LL*DM + h*DHD;

    float acc[4][4] = {};
    for (int k0 = 0; k0 < LL; k0 += 32) {
        __syncthreads();
        // A tile: 64 rows x 32 cols; per-instr warp = 4 rows x 8 float4 (full lines)
        {
            const int c4 = t & 7;      // float4 column 0..7
            const int r0 = t >> 3;     // 0..15
            #pragma unroll
            for (int rr = 0; rr < 4; rr++) {
                const int r = r0 + rr*16;
                float4 v = *(const float4*)&arow[(size_t)r*LL + k0 + c4*4];
                float* d = &As[r*33 + c4*4];
                d[0]=v.x; d[1]=v.y; d[2]=v.z; d[3]=v.w;
            }
            // V tile: 32 x 32
            const int vr = t >> 2;          // 0..31
            const int vc = (t & 3) * 8;     // 0,8,16,24
            const float* vg = Vhead + (size_t)(k0 + vr)*DM + vc;
            float4 x0 = ((const float4*)vg)[0], x1 = ((const float4*)vg)[1];
            float* vd = &Vs[vr*33 + vc];
            vd[0]=x0.x; vd[1]=x0.y; vd[2]=x0.z; vd[3]=x0.w;
            vd[4]=x1.x; vd[5]=x1.y; vd[6]=x1.z; vd[7]=x1.w;
        }
        __syncthreads();
        #pragma unroll
        for (int kk = 0; kk < 32; kk++) {
            float a0 = As[(ty*4+0)*33 + kk];
            float a1 = As[(ty*4+1)*33 + kk];
            float a2 = As[(ty*4+2)*33 + kk];
            float a3 = As[(ty*4+3)*33 + kk];
            float b0 = Vs[kk*33 + tx*4 + 0];
            float b1 = Vs[kk*33 + tx*4 + 1];
            float b2 = Vs[kk*33 + tx*4 + 2];
            float b3 = Vs[kk*33 + tx*4 + 3];
            acc[0][0] += a0*b0; acc[0][1] += a0*b1; acc[0][2] += a0*b2; acc[0][3] += a0*b3;
            acc[1][0] += a1*b0; acc[1][1] += a1*b1; acc[1][2] += a1*b2; acc[1][3] += a1*b3;
            acc[2][0] += a2*b0; acc[2][1] += a2*b1; acc[2][2] += a2*b2; acc[2][3] += a2*b3;
            acc[3][0] += a3*b0; acc[3][1] += a3*b1; acc[3][2] += a3*b2; acc[3][3] += a3*b3;
        }
    }
    #pragma unroll
    for (int i = 0; i < 4; i++) {
        const int q = qt*64 + ty*4 + i;
        float4 o = make_float4(acc[i][0], acc[i][1], acc[i][2], acc[i][3]);
        *(float4*)&g_O[((size_t)b*LL + q)*DM + h*DHD + tx*4] = o;
    }
}

extern "C" void kernel_launch(void* const* d_in, const int* in_sizes, int n_in,
                              void* d_out, int out_size) {
    (void)in_sizes; (void)n_in; (void)out_size;
    const float* queries = (const float*)d_in[0];
    const float* keys    = (const float*)d_in[1];
    const float* values  = (const float*)d_in[2];
    const int*   amask   = (const int*)  d_in[3];
    const float* adj     = (const float*)d_in[4];
    const float* dist    = (const float*)d_in[5];
    const float* Wq      = (const float*)d_in[6];
    const float* Wk      = (const float*)d_in[7];
    const float* Wv      = (const float*)d_in[8];
    const float* Wo      = (const float*)d_in[9];
    const float* wA      = (const float*)d_in[10];
    const float* wD      = (const float*)d_in[11];

    float *dQ, *dK, *dV, *dO;
    cudaGetSymbolAddress((void**)&dQ, g_Q);
    cudaGetSymbolAddress((void**)&dK, g_K);
    cudaGetSymbolAddress((void**)&dV, g_V);
    cudaGetSymbolAddress((void**)&dO, g_O);

    float* out_proj = (float*)d_out;                       // (B, L, 256)
    float* out_attn = (float*)d_out + (size_t)BB*LL*DM;    // (B, H, L, L)

    dim3 gemmGrid(DM/64, (BB*LL)/64);   // (4, 64)
    gemm_nt<<<gemmGrid, 256>>>(queries, Wq, dQ);
    gemm_nt<<<gemmGrid, 256>>>(keys,    Wk, dK);
    gemm_nt<<<gemmGrid, 256>>>(values,  Wv, dV);

    attn_scores_kernel<<<dim3(HH, LL/64, BB*(LL/64)), 256>>>(amask, adj, dist, wA, wD, out_attn);
    softmax_kernel<<<BB*HH*LL, 256>>>(out_attn);
    pv_kernel<<<dim3(LL/64, BB*HH), 128>>>(out_attn);

    gemm_nt<<<gemmGrid, 256>>>(dO, Wo, out_proj);
}